// round 5
// baseline (speedup 1.0000x reference)
#include <cuda_runtime.h>
#include <math.h>

#define NS_N 2048
#define NS_B 16

// log2e-domain split arrays (allocation-free rule: __device__ globals)
//   s' = s*log2e :  g_shi on 2^-10 grid, g_slo residual
//   B' = B*log2e :  g_nbh = -(grid part), g_nbl = -(residual)   [pre-negated]
__device__ float g_shi[NS_B * NS_N];
__device__ float g_slo[NS_B * NS_N];
__device__ float g_nbh[NS_B * NS_N];
__device__ float g_nbl[NS_B * NS_N];

// ---------------- f32x2 packed helpers (sm_103a) ----------------
typedef unsigned long long u64;
__device__ __forceinline__ u64 pk2(float x, float y) {
    u64 r; asm("mov.b64 %0, {%1,%2};" : "=l"(r) : "f"(x), "f"(y)); return r;
}
__device__ __forceinline__ float2 upk2(u64 v) {
    float2 r; asm("mov.b64 {%0,%1}, %2;" : "=f"(r.x), "=f"(r.y) : "l"(v)); return r;
}
__device__ __forceinline__ u64 fma2(u64 a, u64 b, u64 c) {
    u64 d; asm("fma.rn.f32x2 %0, %1, %2, %3;" : "=l"(d) : "l"(a), "l"(b), "l"(c)); return d;
}
__device__ __forceinline__ u64 add2(u64 a, u64 b) {
    u64 d; asm("add.rn.f32x2 %0, %1, %2;" : "=l"(d) : "l"(a), "l"(b)); return d;
}
__device__ __forceinline__ float ex2(float x) {
    float r; asm("ex2.approx.ftz.f32 %0, %1;" : "=f"(r) : "f"(x)); return r;
}

// ---------------------------------------------------------------------------
// Kernel 1: Bsum[b][j] = sum_k |s[b][j] - s[b][k]|
// Warp per j. Per-lane: 4 plain f32 accumulators (16 O(1)-magnitude terms
// each -> ~1e-5 error), combined and warp-reduced in f64 (exact enough).
// Lane 0 emits log2e-domain 2^-10-grid splits of s and -B.
// grid: (N/8, B), block 256
// ---------------------------------------------------------------------------
__global__ __launch_bounds__(256) void ns_bsum_kernel(const float* __restrict__ scores) {
    __shared__ float s[NS_N];
    const int b = blockIdx.y;
    {
        const float4* sp4 = (const float4*)(scores + b * NS_N);
        float4* s4 = (float4*)s;
        for (int k = threadIdx.x; k < NS_N / 4; k += 256)
            s4[k] = sp4[k];
    }
    __syncthreads();

    const int warp = threadIdx.x >> 5;
    const int lane = threadIdx.x & 31;
    const int j = blockIdx.x * 8 + warp;
    const float sj = s[j];

    const float2* s2 = (const float2*)s;
    float a0 = 0.0f, a1 = 0.0f, a2 = 0.0f, a3 = 0.0f;
#pragma unroll
    for (int t = 0; t < 32; t += 2) {
        float2 v0 = s2[lane + (t << 5)];
        float2 v1 = s2[lane + ((t + 1) << 5)];
        a0 += fabsf(sj - v0.x);
        a1 += fabsf(sj - v0.y);
        a2 += fabsf(sj - v1.x);
        a3 += fabsf(sj - v1.y);
    }
    double d = ((double)a0 + (double)a1) + ((double)a2 + (double)a3);
#pragma unroll
    for (int o = 16; o > 0; o >>= 1)
        d += __shfl_xor_sync(0xFFFFFFFFu, d, o);

    if (lane == 0) {
        const double LOG2E = 1.4426950408889634074;
        double Bp = d * LOG2E;
        double gB = rint(Bp * 1024.0);
        float bh = (float)(gB * (1.0 / 1024.0));
        float bl = (float)(Bp - (double)bh);
        double sp = (double)sj * LOG2E;
        double gS = rint(sp * 1024.0);
        float sh = (float)(gS * (1.0 / 1024.0));
        float sl = (float)(sp - (double)sh);
        g_shi[b * NS_N + j] = sh;
        g_slo[b * NS_N + j] = sl;
        g_nbh[b * NS_N + j] = -bh;
        g_nbl[b * NS_N + j] = -bl;
    }
}

// ---------------------------------------------------------------------------
// Kernel 2: out[b][i][j] = softmax_j( scale_i * s[b][j] - Bsum[b][j] )
// Block = 4 rows x full 2048 columns, 512 threads. Each thread owns ONE
// float4 column slice: the 4 split arrays are loaded ONCE from global
// (L2-hot) into registers and reused for the max pass AND all 4 rows.
// No data SMEM -> L1 traffic ~8B per output element (LDG amortized + STG).
// Cross-warp max/sum via tiny SMEM tree (warps 0..3 reduce 16 partials).
// exp = ex2( (h - m) + l ); h, m exact on the 2^-10 grid near the max.
// grid: (N/4, B), block 512, 2 CTAs/SM.
// ---------------------------------------------------------------------------
__global__ __launch_bounds__(512, 2) void ns_softmax_kernel(float* __restrict__ out) {
    __shared__ float red[64];      // [r*16 + w]
    __shared__ float finm[4];
    __shared__ float fins[4];

    const int b = blockIdx.y;
    const int ibase = blockIdx.x * 4;
    const int tid = threadIdx.x;
    const int w = tid >> 5;
    const int lane = tid & 31;

    // one float4 per thread per array, register-resident for the whole kernel
    const float4 sh4  = ((const float4*)(g_shi + b * NS_N))[tid];
    const float4 sl4  = ((const float4*)(g_slo + b * NS_N))[tid];
    const float4 nbh4 = ((const float4*)(g_nbh + b * NS_N))[tid];
    const float4 nbl4 = ((const float4*)(g_nbl + b * NS_N))[tid];

    float sc[4], mx[4];
#pragma unroll
    for (int r = 0; r < 4; ++r) {
        sc[r] = (float)(NS_N - 1 - 2 * (ibase + r));
        mx[r] = -INFINITY;
    }

    // ---- pass A: row maxima of exact-grid h ----
#pragma unroll
    for (int r = 0; r < 4; ++r) {
        const float s = sc[r];
        float h0 = fmaf(s, sh4.x, nbh4.x);
        float h1 = fmaf(s, sh4.y, nbh4.y);
        float h2 = fmaf(s, sh4.z, nbh4.z);
        float h3 = fmaf(s, sh4.w, nbh4.w);
        mx[r] = fmaxf(fmaxf(h0, h1), fmaxf(h2, h3));
    }
#pragma unroll
    for (int r = 0; r < 4; ++r) {
#pragma unroll
        for (int o = 16; o > 0; o >>= 1)
            mx[r] = fmaxf(mx[r], __shfl_xor_sync(0xFFFFFFFFu, mx[r], o));
        if (lane == 0) red[r * 16 + w] = mx[r];
    }
    __syncthreads();
    if (w < 4) {
        float v = (lane < 16) ? red[w * 16 + lane] : -INFINITY;
#pragma unroll
        for (int o = 8; o > 0; o >>= 1)
            v = fmaxf(v, __shfl_xor_sync(0xFFFFFFFFu, v, o));
        if (lane == 0) finm[w] = v;
    }
    __syncthreads();

    // ---- pass B: exp into registers (one float4 per row), per-row sums ----
    float4 t[4];
    float sum[4];
#pragma unroll
    for (int r = 0; r < 4; ++r) {
        const float m = finm[r];
        const u64 sc2 = pk2(sc[r], sc[r]);
        const u64 nm2 = pk2(-m, -m);
        u64 h01 = fma2(sc2, pk2(sh4.x, sh4.y), pk2(nbh4.x, nbh4.y));
        u64 h23 = fma2(sc2, pk2(sh4.z, sh4.w), pk2(nbh4.z, nbh4.w));
        u64 l01 = fma2(sc2, pk2(sl4.x, sl4.y), pk2(nbl4.x, nbl4.y));
        u64 l23 = fma2(sc2, pk2(sl4.z, sl4.w), pk2(nbl4.z, nbl4.w));
        // (h - m) first (exact where it matters), then + l
        u64 a01 = add2(add2(h01, nm2), l01);
        u64 a23 = add2(add2(h23, nm2), l23);
        float2 f01 = upk2(a01), f23 = upk2(a23);
        float e0 = ex2(f01.x), e1 = ex2(f01.y), e2 = ex2(f23.x), e3 = ex2(f23.y);
        t[r] = make_float4(e0, e1, e2, e3);
        sum[r] = (e0 + e1) + (e2 + e3);
    }
#pragma unroll
    for (int r = 0; r < 4; ++r) {
#pragma unroll
        for (int o = 16; o > 0; o >>= 1)
            sum[r] += __shfl_xor_sync(0xFFFFFFFFu, sum[r], o);
        if (lane == 0) red[r * 16 + w] = sum[r];
    }
    __syncthreads();
    if (w < 4) {
        float v = (lane < 16) ? red[w * 16 + lane] : 0.0f;
#pragma unroll
        for (int o = 8; o > 0; o >>= 1)
            v += __shfl_xor_sync(0xFFFFFFFFu, v, o);
        if (lane == 0) fins[w] = v;
    }
    __syncthreads();

    // ---- normalize + streaming float4 stores ----
#pragma unroll
    for (int r = 0; r < 4; ++r) {
        const float inv = __frcp_rn(fins[r]);
        float4 tv = t[r];
        tv.x *= inv; tv.y *= inv; tv.z *= inv; tv.w *= inv;
        float4* o4 = (float4*)(out + ((size_t)b * NS_N + (size_t)(ibase + r)) * NS_N);
        __stcs(&o4[tid], tv);
    }
}

extern "C" void kernel_launch(void* const* d_in, const int* in_sizes, int n_in,
                              void* d_out, int out_size) {
    const float* scores = (const float*)d_in[0];
    float* out = (float*)d_out;
    (void)in_sizes; (void)n_in; (void)out_size;

    dim3 g1(NS_N / 8, NS_B);
    ns_bsum_kernel<<<g1, 256>>>(scores);

    dim3 g2(NS_N / 4, NS_B);
    ns_softmax_kernel<<<g2, 512>>>(out);
}

// round 6
// speedup vs baseline: 1.9183x; 1.9183x over previous
#include <cuda_runtime.h>
#include <math.h>

#define NS_N 2048
#define NS_B 16

// log2e-domain split arrays (allocation-free rule: __device__ globals)
//   s' = s*log2e :  g_shi on 2^-10 grid, g_slo residual
//   B' = B*log2e :  g_nbh = -(grid part), g_nbl = -(residual)   [pre-negated]
__device__ float g_shi[NS_B * NS_N];
__device__ float g_slo[NS_B * NS_N];
__device__ float g_nbh[NS_B * NS_N];
__device__ float g_nbl[NS_B * NS_N];

__device__ __forceinline__ float ex2(float x) {
    float r; asm("ex2.approx.ftz.f32 %0, %1;" : "=f"(r) : "f"(x)); return r;
}

// ---------------------------------------------------------------------------
// Kernel 1: Bsum[b][j] = sum_k |s[b][j] - s[b][k]|
// Thread per j. k-loop reads s via BROADCAST float4 LDS (all lanes same
// address -> conflict-free, 1/32 the LDS traffic of lane-strided reads).
// 32-element f32 partials (err ~1e-5) flushed into ONE f64 accumulator
// (64 DADDs/thread, fp64 pipe overlaps the FADD stream). No warp reduce.
// Epilogue: log2e-domain 2^-10-grid splits of s and -B per thread.
// grid: (N/256, B), block 256
// ---------------------------------------------------------------------------
__global__ __launch_bounds__(256) void ns_bsum_kernel(const float* __restrict__ scores) {
    __shared__ float s[NS_N];
    const int b = blockIdx.y;
    {
        const float4* sp4 = (const float4*)(scores + b * NS_N);
        float4* s4s = (float4*)s;
        for (int k = threadIdx.x; k < NS_N / 4; k += 256)
            s4s[k] = sp4[k];
    }
    __syncthreads();

    const int j = blockIdx.x * 256 + threadIdx.x;
    const float sj = s[j];
    const float4* s4 = (const float4*)s;

    double dacc = 0.0;
#pragma unroll 2
    for (int it = 0; it < 64; ++it) {
        float p0 = 0.0f, p1 = 0.0f, p2 = 0.0f, p3 = 0.0f;
#pragma unroll
        for (int u = 0; u < 8; ++u) {
            const float4 v = s4[it * 8 + u];     // broadcast
            p0 += fabsf(sj - v.x);
            p1 += fabsf(sj - v.y);
            p2 += fabsf(sj - v.z);
            p3 += fabsf(sj - v.w);
        }
        dacc += (double)((p0 + p1) + (p2 + p3));
    }

    const double LOG2E = 1.4426950408889634074;
    double Bp = dacc * LOG2E;
    float bh = (float)(rint(Bp * 1024.0) * (1.0 / 1024.0));
    float bl = (float)(Bp - (double)bh);
    double sp = (double)sj * LOG2E;
    float sh = (float)(rint(sp * 1024.0) * (1.0 / 1024.0));
    float sl = (float)(sp - (double)sh);

    g_shi[b * NS_N + j] = sh;
    g_slo[b * NS_N + j] = sl;
    g_nbh[b * NS_N + j] = -bh;
    g_nbl[b * NS_N + j] = -bl;
}

// ---------------------------------------------------------------------------
// Kernel 2: out[b][i][j] = softmax_j( scale_i * s[b][j] - Bsum[b][j] )
// Block = 4 rows x 2048 cols, 512 threads, one float4 column slice/thread,
// split arrays register-resident (loaded once from L2-hot global).
// ROW RECURRENCE: x_{r+1} = x_r - 2 s'_j  =>  e_{r+1} = e_r * d_j with
// d_j = 2^(-2 s'_j). Per-row scalar shifts cancel in softmax, so only
// row 0 needs the max-subtraction and the exact-split path:
//   e0 = ex2( (h - m) + l ),  h = fma(sc0, s_hi, -B_hi) exact on 2^-10 grid.
// Range: e0 <= 2, |2s'| <= 13.3 -> e3 <= 2^41 (safe); flushed-to-0 elements
// are provably < 2^-46 of their row max (irrelevant).
// grid: (N/4, B), block 512, 2 CTAs/SM.
// ---------------------------------------------------------------------------
__global__ __launch_bounds__(512, 2) void ns_softmax_kernel(float* __restrict__ out) {
    __shared__ float red[64];     // [r*16 + w] for sums; [w] for max
    __shared__ float finm;
    __shared__ float fins[4];

    const int b = blockIdx.y;
    const int ibase = blockIdx.x * 4;
    const int tid = threadIdx.x;
    const int w = tid >> 5;
    const int lane = tid & 31;

    const float4 sh4  = ((const float4*)(g_shi + b * NS_N))[tid];
    const float4 sl4  = ((const float4*)(g_slo + b * NS_N))[tid];
    const float4 nbh4 = ((const float4*)(g_nbh + b * NS_N))[tid];
    const float4 nbl4 = ((const float4*)(g_nbl + b * NS_N))[tid];

    const float sc0 = (float)(NS_N - 1 - 2 * ibase);

    // ---- row-0 grid logits (exact) + single block max ----
    float4 h4;
    h4.x = fmaf(sc0, sh4.x, nbh4.x);
    h4.y = fmaf(sc0, sh4.y, nbh4.y);
    h4.z = fmaf(sc0, sh4.z, nbh4.z);
    h4.w = fmaf(sc0, sh4.w, nbh4.w);
    float mx = fmaxf(fmaxf(h4.x, h4.y), fmaxf(h4.z, h4.w));
#pragma unroll
    for (int o = 16; o > 0; o >>= 1)
        mx = fmaxf(mx, __shfl_xor_sync(0xFFFFFFFFu, mx, o));
    if (lane == 0) red[w] = mx;
    __syncthreads();
    if (w == 0) {
        float v = (lane < 16) ? red[lane] : -INFINITY;
#pragma unroll
        for (int o = 8; o > 0; o >>= 1)
            v = fmaxf(v, __shfl_xor_sync(0xFFFFFFFFu, v, o));
        if (lane == 0) finm = v;
    }
    __syncthreads();
    const float m = finm;

    // ---- row 0: exact-split exp; d = 2^(-2 s'); rows 1..3 by recurrence ----
    float4 e0, e1, e2, e3, d4;
    {
        float lx = fmaf(sc0, sl4.x, nbl4.x);
        float ly = fmaf(sc0, sl4.y, nbl4.y);
        float lz = fmaf(sc0, sl4.z, nbl4.z);
        float lw = fmaf(sc0, sl4.w, nbl4.w);
        e0.x = ex2((h4.x - m) + lx);
        e0.y = ex2((h4.y - m) + ly);
        e0.z = ex2((h4.z - m) + lz);
        e0.w = ex2((h4.w - m) + lw);
        d4.x = ex2(fmaf(-2.0f, sh4.x, -2.0f * sl4.x));
        d4.y = ex2(fmaf(-2.0f, sh4.y, -2.0f * sl4.y));
        d4.z = ex2(fmaf(-2.0f, sh4.z, -2.0f * sl4.z));
        d4.w = ex2(fmaf(-2.0f, sh4.w, -2.0f * sl4.w));
        e1.x = e0.x * d4.x; e1.y = e0.y * d4.y; e1.z = e0.z * d4.z; e1.w = e0.w * d4.w;
        e2.x = e1.x * d4.x; e2.y = e1.y * d4.y; e2.z = e1.z * d4.z; e2.w = e1.w * d4.w;
        e3.x = e2.x * d4.x; e3.y = e2.y * d4.y; e3.z = e2.z * d4.z; e3.w = e2.w * d4.w;
    }

    // ---- per-row sums (4 block reductions sharing one sync pair) ----
    float sum[4];
    sum[0] = (e0.x + e0.y) + (e0.z + e0.w);
    sum[1] = (e1.x + e1.y) + (e1.z + e1.w);
    sum[2] = (e2.x + e2.y) + (e2.z + e2.w);
    sum[3] = (e3.x + e3.y) + (e3.z + e3.w);
#pragma unroll
    for (int r = 0; r < 4; ++r) {
#pragma unroll
        for (int o = 16; o > 0; o >>= 1)
            sum[r] += __shfl_xor_sync(0xFFFFFFFFu, sum[r], o);
    }
    if (lane == 0) {
        red[0 * 16 + w] = sum[0];
        red[1 * 16 + w] = sum[1];
        red[2 * 16 + w] = sum[2];
        red[3 * 16 + w] = sum[3];
    }
    __syncthreads();
    if (w < 4) {
        float v = (lane < 16) ? red[w * 16 + lane] : 0.0f;
#pragma unroll
        for (int o = 8; o > 0; o >>= 1)
            v += __shfl_xor_sync(0xFFFFFFFFu, v, o);
        if (lane == 0) fins[w] = v;
    }
    __syncthreads();

    // ---- normalize + streaming float4 stores ----
    float4* o4 = (float4*)(out + ((size_t)b * NS_N + (size_t)ibase) * NS_N);
    {
        const float inv = __frcp_rn(fins[0]);
        float4 tv = e0; tv.x *= inv; tv.y *= inv; tv.z *= inv; tv.w *= inv;
        __stcs(&o4[tid], tv);
    }
    {
        const float inv = __frcp_rn(fins[1]);
        float4 tv = e1; tv.x *= inv; tv.y *= inv; tv.z *= inv; tv.w *= inv;
        __stcs(&o4[512 + tid], tv);
    }
    {
        const float inv = __frcp_rn(fins[2]);
        float4 tv = e2; tv.x *= inv; tv.y *= inv; tv.z *= inv; tv.w *= inv;
        __stcs(&o4[1024 + tid], tv);
    }
    {
        const float inv = __frcp_rn(fins[3]);
        float4 tv = e3; tv.x *= inv; tv.y *= inv; tv.z *= inv; tv.w *= inv;
        __stcs(&o4[1536 + tid], tv);
    }
}

extern "C" void kernel_launch(void* const* d_in, const int* in_sizes, int n_in,
                              void* d_out, int out_size) {
    const float* scores = (const float*)d_in[0];
    float* out = (float*)d_out;
    (void)in_sizes; (void)n_in; (void)out_size;

    dim3 g1(NS_N / 256, NS_B);
    ns_bsum_kernel<<<g1, 256>>>(scores);

    dim3 g2(NS_N / 4, NS_B);
    ns_softmax_kernel<<<g2, 512>>>(out);
}

// round 7
// speedup vs baseline: 1.9763x; 1.0303x over previous
#include <cuda_runtime.h>
#include <math.h>

#define NS_N 2048
#define NS_B 16

// log2e-domain split arrays (allocation-free rule: __device__ globals)
//   s' = s*log2e :  g_shi on 2^-10 grid, g_slo residual
//   B' = B*log2e :  g_nbh = -(grid part), g_nbl = -(residual)   [pre-negated]
__device__ float g_shi[NS_B * NS_N];
__device__ float g_slo[NS_B * NS_N];
__device__ float g_nbh[NS_B * NS_N];
__device__ float g_nbl[NS_B * NS_N];

typedef unsigned long long u64;
__device__ __forceinline__ u64 pk2(float x, float y) {
    u64 r; asm("mov.b64 %0, {%1,%2};" : "=l"(r) : "f"(x), "f"(y)); return r;
}
__device__ __forceinline__ float2 upk2(u64 v) {
    float2 r; asm("mov.b64 {%0,%1}, %2;" : "=f"(r.x), "=f"(r.y) : "l"(v)); return r;
}
__device__ __forceinline__ u64 add2(u64 a, u64 b) {
    u64 d; asm("add.rn.f32x2 %0, %1, %2;" : "=l"(d) : "l"(a), "l"(b)); return d;
}
__device__ __forceinline__ u64 abs2(u64 a) {         // clear both sign bits (2x LOP3, alu pipe)
    return a & 0x7FFFFFFF7FFFFFFFull;
}
__device__ __forceinline__ float ex2(float x) {
    float r; asm("ex2.approx.ftz.f32 %0, %1;" : "=f"(r) : "f"(x)); return r;
}

// ---------------------------------------------------------------------------
// Kernel 1: Bsum[b][j] = sum_k |s[b][j] - s[b][k]|
// Thread per j. Packed f32x2: SMEM holds -s pre-packed; per 2 elements one
// add2 (sj + (-sk)), one abs2 (64-bit AND, alu pipe), one add2 accumulate.
// 2 accumulators x 8 packed = 32-elem f32x2 partials (err ~1e-5), combined
// and folded into a Neumaier-compensated f32 grand sum (ulp-exact).
// f64 only in the once-per-thread epilogue (grid splits).
// grid: (N/256, B), block 256
// ---------------------------------------------------------------------------
__global__ __launch_bounds__(256) void ns_bsum_kernel(const float* __restrict__ scores) {
    __shared__ float s[NS_N];
    __shared__ u64 sneg2[NS_N / 2];
    const int b = blockIdx.y;
    {
        const float4* sp4 = (const float4*)(scores + b * NS_N);
        for (int k = threadIdx.x; k < NS_N / 4; k += 256) {
            float4 v = sp4[k];
            ((float4*)s)[k] = v;
            sneg2[2 * k + 0] = pk2(-v.x, -v.y);
            sneg2[2 * k + 1] = pk2(-v.z, -v.w);
        }
    }
    __syncthreads();

    const int j = blockIdx.x * 256 + threadIdx.x;
    const float sj = s[j];
    const u64 sj2 = pk2(sj, sj);

    float sum = 0.0f, comp = 0.0f;
#pragma unroll 2
    for (int it = 0; it < 64; ++it) {
        u64 A = 0ull, B = 0ull;        // 0ull == packed {0.0f, 0.0f}
#pragma unroll
        for (int u = 0; u < 8; ++u) {
            A = add2(A, abs2(add2(sj2, sneg2[it * 16 + u])));       // broadcast LDS.64
            B = add2(B, abs2(add2(sj2, sneg2[it * 16 + 8 + u])));
        }
        float2 a = upk2(A), bb = upk2(B);
        float f = (a.x + a.y) + (bb.x + bb.y);
        // Neumaier compensated add
        float t = sum + f;
        comp += (fabsf(sum) >= fabsf(f)) ? ((sum - t) + f) : ((f - t) + sum);
        sum = t;
    }
    double d = (double)sum + (double)comp;

    const double LOG2E = 1.4426950408889634074;
    double Bp = d * LOG2E;
    float bh = (float)(rint(Bp * 1024.0) * (1.0 / 1024.0));
    float bl = (float)(Bp - (double)bh);
    double sp = (double)sj * LOG2E;
    float sh = (float)(rint(sp * 1024.0) * (1.0 / 1024.0));
    float sl = (float)(sp - (double)sh);

    g_shi[b * NS_N + j] = sh;
    g_slo[b * NS_N + j] = sl;
    g_nbh[b * NS_N + j] = -bh;
    g_nbl[b * NS_N + j] = -bl;
}

// ---------------------------------------------------------------------------
// Kernel 2: out[b][i][j] = softmax_j( scale_i * s[b][j] - Bsum[b][j] )
// Block = 4 rows x 2048 cols, 512 threads, one float4 column slice/thread,
// split arrays register-resident (loaded once from L2-hot global).
// ROW RECURRENCE: e_{r+1} = e_r * d_j, d_j = 2^(-2 s'_j); per-row scalar
// shifts cancel in softmax, so only row 0 needs max-subtraction + exact path.
// grid: (N/4, B), block 512, 3 CTAs/SM -> 48 warps = 100% occupancy.
// ---------------------------------------------------------------------------
__global__ __launch_bounds__(512, 3) void ns_softmax_kernel(float* __restrict__ out) {
    __shared__ float red[64];     // [r*16 + w] for sums; [w] for max
    __shared__ float finm;
    __shared__ float fins[4];

    const int b = blockIdx.y;
    const int ibase = blockIdx.x * 4;
    const int tid = threadIdx.x;
    const int w = tid >> 5;
    const int lane = tid & 31;

    const float4 sh4  = ((const float4*)(g_shi + b * NS_N))[tid];
    const float4 sl4  = ((const float4*)(g_slo + b * NS_N))[tid];
    const float4 nbh4 = ((const float4*)(g_nbh + b * NS_N))[tid];
    const float4 nbl4 = ((const float4*)(g_nbl + b * NS_N))[tid];

    const float sc0 = (float)(NS_N - 1 - 2 * ibase);

    // ---- row-0 grid logits (exact) + single block max ----
    float4 h4;
    h4.x = fmaf(sc0, sh4.x, nbh4.x);
    h4.y = fmaf(sc0, sh4.y, nbh4.y);
    h4.z = fmaf(sc0, sh4.z, nbh4.z);
    h4.w = fmaf(sc0, sh4.w, nbh4.w);
    float mx = fmaxf(fmaxf(h4.x, h4.y), fmaxf(h4.z, h4.w));
#pragma unroll
    for (int o = 16; o > 0; o >>= 1)
        mx = fmaxf(mx, __shfl_xor_sync(0xFFFFFFFFu, mx, o));
    if (lane == 0) red[w] = mx;
    __syncthreads();
    if (w == 0) {
        float v = (lane < 16) ? red[lane] : -INFINITY;
#pragma unroll
        for (int o = 8; o > 0; o >>= 1)
            v = fmaxf(v, __shfl_xor_sync(0xFFFFFFFFu, v, o));
        if (lane == 0) finm = v;
    }
    __syncthreads();
    const float m = finm;

    // ---- row 0: exact-split exp; d = 2^(-2 s'); rows 1..3 by recurrence ----
    float4 e0, e1, e2, e3, d4;
    {
        float lx = fmaf(sc0, sl4.x, nbl4.x);
        float ly = fmaf(sc0, sl4.y, nbl4.y);
        float lz = fmaf(sc0, sl4.z, nbl4.z);
        float lw = fmaf(sc0, sl4.w, nbl4.w);
        e0.x = ex2((h4.x - m) + lx);
        e0.y = ex2((h4.y - m) + ly);
        e0.z = ex2((h4.z - m) + lz);
        e0.w = ex2((h4.w - m) + lw);
        d4.x = ex2(fmaf(-2.0f, sh4.x, -2.0f * sl4.x));
        d4.y = ex2(fmaf(-2.0f, sh4.y, -2.0f * sl4.y));
        d4.z = ex2(fmaf(-2.0f, sh4.z, -2.0f * sl4.z));
        d4.w = ex2(fmaf(-2.0f, sh4.w, -2.0f * sl4.w));
        e1.x = e0.x * d4.x; e1.y = e0.y * d4.y; e1.z = e0.z * d4.z; e1.w = e0.w * d4.w;
        e2.x = e1.x * d4.x; e2.y = e1.y * d4.y; e2.z = e1.z * d4.z; e2.w = e1.w * d4.w;
        e3.x = e2.x * d4.x; e3.y = e2.y * d4.y; e3.z = e2.z * d4.z; e3.w = e2.w * d4.w;
    }

    // ---- per-row sums (4 block reductions sharing one sync pair) ----
    float sum[4];
    sum[0] = (e0.x + e0.y) + (e0.z + e0.w);
    sum[1] = (e1.x + e1.y) + (e1.z + e1.w);
    sum[2] = (e2.x + e2.y) + (e2.z + e2.w);
    sum[3] = (e3.x + e3.y) + (e3.z + e3.w);
#pragma unroll
    for (int r = 0; r < 4; ++r) {
#pragma unroll
        for (int o = 16; o > 0; o >>= 1)
            sum[r] += __shfl_xor_sync(0xFFFFFFFFu, sum[r], o);
    }
    if (lane == 0) {
        red[0 * 16 + w] = sum[0];
        red[1 * 16 + w] = sum[1];
        red[2 * 16 + w] = sum[2];
        red[3 * 16 + w] = sum[3];
    }
    __syncthreads();
    if (w < 4) {
        float v = (lane < 16) ? red[w * 16 + lane] : 0.0f;
#pragma unroll
        for (int o = 8; o > 0; o >>= 1)
            v += __shfl_xor_sync(0xFFFFFFFFu, v, o);
        if (lane == 0) fins[w] = v;
    }
    __syncthreads();

    // ---- normalize + streaming float4 stores ----
    float4* o4 = (float4*)(out + ((size_t)b * NS_N + (size_t)ibase) * NS_N);
    {
        const float inv = __frcp_rn(fins[0]);
        float4 tv = e0; tv.x *= inv; tv.y *= inv; tv.z *= inv; tv.w *= inv;
        __stcs(&o4[tid], tv);
    }
    {
        const float inv = __frcp_rn(fins[1]);
        float4 tv = e1; tv.x *= inv; tv.y *= inv; tv.z *= inv; tv.w *= inv;
        __stcs(&o4[512 + tid], tv);
    }
    {
        const float inv = __frcp_rn(fins[2]);
        float4 tv = e2; tv.x *= inv; tv.y *= inv; tv.z *= inv; tv.w *= inv;
        __stcs(&o4[1024 + tid], tv);
    }
    {
        const float inv = __frcp_rn(fins[3]);
        float4 tv = e3; tv.x *= inv; tv.y *= inv; tv.z *= inv; tv.w *= inv;
        __stcs(&o4[1536 + tid], tv);
    }
}

extern "C" void kernel_launch(void* const* d_in, const int* in_sizes, int n_in,
                              void* d_out, int out_size) {
    const float* scores = (const float*)d_in[0];
    float* out = (float*)d_out;
    (void)in_sizes; (void)n_in; (void)out_size;

    dim3 g1(NS_N / 256, NS_B);
    ns_bsum_kernel<<<g1, 256>>>(scores);

    dim3 g2(NS_N / 4, NS_B);
    ns_softmax_kernel<<<g2, 512>>>(out);
}